// round 12
// baseline (speedup 1.0000x reference)
#include <cuda_runtime.h>
#include <math.h>

// Geometry: 64 images of 512*512*3 = 786432 floats (3 MB each)
#define N_IMG 64
#define IMG_ELEMS 786432
#define IMG_VEC4  196608                 // IMG_ELEMS / 4

#define GROUPS 4
#define IMG_PER_GRP 16                   // 48 MB per group; 2 groups (96 MB) < 126 MB L2

#define BLOCKS_PER_IMG 24
#define CHUNK_VEC4 (IMG_VEC4 / BLOCKS_PER_IMG)      // 8192
#define THREADS 256
#define NBLK (IMG_PER_GRP * BLOCKS_PER_IMG)         // 384

// Scratch (no allocations allowed)
__device__ float2 g_partials[N_IMG * BLOCKS_PER_IMG];

// One pipeline stage: reduce group `grp` (DRAM reads) while applying group
// `grp-1` (L2 reads + DRAM writes). The previous launch produced grp-1's
// partials; the launch boundary makes them visible — no device-side sync.
__global__ __launch_bounds__(THREADS)
void stage_kernel(const float4* __restrict__ in, float4* __restrict__ out,
                  int grp, int do_reduce, int do_apply) {
    const int limg  = blockIdx.x / BLOCKS_PER_IMG;
    const int chunk = blockIdx.x % BLOCKS_PER_IMG;
    const int tid   = threadIdx.x;
    const int lane  = tid & 31, wid = tid >> 5;

    const int rimg = grp * IMG_PER_GRP + limg;            // image being reduced
    const int aimg = (grp - 1) * IMG_PER_GRP + limg;      // image being applied
    const size_t rbase = (size_t)rimg * IMG_VEC4 + (size_t)chunk * CHUNK_VEC4;
    const size_t abase = (size_t)aimg * IMG_VEC4 + (size_t)chunk * CHUNK_VEC4;

    // ---- Inline finalize for the apply image (fixed-order tree, deterministic) ----
    __shared__ float2 sh_ss;
    if (do_apply && tid < 32) {
        float s = 0.f, sq = 0.f;
        if (lane < BLOCKS_PER_IMG) {
            float2 p = g_partials[aimg * BLOCKS_PER_IMG + lane];
            s = p.x; sq = p.y;
        }
        #pragma unroll
        for (int off = 16; off > 0; off >>= 1) {
            s  += __shfl_down_sync(0xffffffffu, s,  off);
            sq += __shfl_down_sync(0xffffffffu, sq, off);
        }
        if (lane == 0) {
            const float inv_n = 1.0f / (float)IMG_ELEMS;
            float mean = s * inv_n;
            float var  = sq * inv_n - mean * mean;
            float stddev = sqrtf(fmaxf(var, 0.0f));
            const float min_std = 1.0f / sqrtf((float)IMG_ELEMS);
            float scale = 1.0f / fmaxf(stddev, min_std);
            sh_ss = make_float2(scale, -mean * scale);
        }
    }
    __syncthreads();
    const float scale = do_apply ? sh_ss.x : 0.f;
    const float shift = do_apply ? sh_ss.y : 0.f;

    float s = 0.f, sq = 0.f;

    if (do_reduce && do_apply) {
        // Fused loop: DRAM read (next group) + L2 read + DRAM write per iter.
        #pragma unroll 4
        for (int i = tid; i < CHUNK_VEC4; i += THREADS) {
            float4 a = __ldcg(in + rbase + i);   // DRAM miss -> fills L2 for next stage
            float4 b = __ldcs(in + abase + i);   // L2 hit (cached by prev stage), dead after
            s  += (a.x + a.y) + (a.z + a.w);
            sq += (a.x * a.x + a.y * a.y) + (a.z * a.z + a.w * a.w);
            float4 r;
            r.x = fmaf(b.x, scale, shift);
            r.y = fmaf(b.y, scale, shift);
            r.z = fmaf(b.z, scale, shift);
            r.w = fmaf(b.w, scale, shift);
            __stcs(out + abase + i, r);          // evict-first: spare the residue
        }
    } else if (do_reduce) {
        #pragma unroll 8
        for (int i = tid; i < CHUNK_VEC4; i += THREADS) {
            float4 a = __ldcg(in + rbase + i);
            s  += (a.x + a.y) + (a.z + a.w);
            sq += (a.x * a.x + a.y * a.y) + (a.z * a.z + a.w * a.w);
        }
    } else {
        #pragma unroll 8
        for (int i = tid; i < CHUNK_VEC4; i += THREADS) {
            float4 b = __ldcs(in + abase + i);
            float4 r;
            r.x = fmaf(b.x, scale, shift);
            r.y = fmaf(b.y, scale, shift);
            r.z = fmaf(b.z, scale, shift);
            r.w = fmaf(b.w, scale, shift);
            __stcs(out + abase + i, r);
        }
    }

    // ---- Block reduction of (s, sq) for the reduced group ----
    if (do_reduce) {
        #pragma unroll
        for (int off = 16; off > 0; off >>= 1) {
            s  += __shfl_down_sync(0xffffffffu, s,  off);
            sq += __shfl_down_sync(0xffffffffu, sq, off);
        }
        __shared__ float2 warp_red[THREADS / 32];
        if (lane == 0) warp_red[wid] = make_float2(s, sq);
        __syncthreads();
        if (wid == 0) {
            float2 v = (lane < THREADS / 32) ? warp_red[lane] : make_float2(0.f, 0.f);
            s = v.x; sq = v.y;
            #pragma unroll
            for (int off = 4; off > 0; off >>= 1) {
                s  += __shfl_down_sync(0xffffffffu, s,  off);
                sq += __shfl_down_sync(0xffffffffu, sq, off);
            }
            if (lane == 0) g_partials[rimg * BLOCKS_PER_IMG + chunk] = make_float2(s, sq);
        }
    }
}

extern "C" void kernel_launch(void* const* d_in, const int* in_sizes, int n_in,
                              void* d_out, int out_size) {
    const float4* in = (const float4*)d_in[0];
    float4* out = (float4*)d_out;

    // Pipeline: K0 reduces g0; K(g) applies g-1 while reducing g; K4 applies g3.
    stage_kernel<<<NBLK, THREADS>>>(in, out, 0, 1, 0);
    for (int g = 1; g < GROUPS; ++g)
        stage_kernel<<<NBLK, THREADS>>>(in, out, g, 1, 1);
    stage_kernel<<<NBLK, THREADS>>>(in, out, GROUPS, 0, 1);
}

// round 14
// speedup vs baseline: 1.3231x; 1.3231x over previous
#include <cuda_runtime.h>
#include <math.h>

// Geometry: 64 images of 512*512*3 = 786432 floats (3 MB each)
#define N_IMG 64
#define IMG_ELEMS 786432
#define IMG_VEC4  196608                 // IMG_ELEMS / 4

#define GROUPS 4
#define IMG_PER_GRP 16                   // 48 MB/group; residue+fill = 96 MB < 126 MB L2

// Reduce shape (per group)
#define BLOCKS_PER_IMG 24
#define CHUNK_VEC4 (IMG_VEC4 / BLOCKS_PER_IMG)          // 8192
#define RED_THREADS 256
#define RED_BLOCKS (IMG_PER_GRP * BLOCKS_PER_IMG)       // 384

// Apply shape (per group) — R6/R8 best config
#define APPLY_THREADS 256
#define V4_PER_THREAD 4
#define V4_PER_BLOCK (APPLY_THREADS * V4_PER_THREAD)    // 1024
#define APPLY_BLOCKS_PER_IMG (IMG_VEC4 / V4_PER_BLOCK)  // 192
#define APPLY_BLOCKS (IMG_PER_GRP * APPLY_BLOCKS_PER_IMG) // 3072

// Scratch (no allocations allowed)
__device__ float2 g_partials[N_IMG * BLOCKS_PER_IMG];

// -------- Reduce one group: per-chunk (sum, sumsq); fills L2 with the group --------
// Independent of the preceding apply launch; with PDL it overlaps it.
__global__ __launch_bounds__(RED_THREADS)
void partial_reduce_kernel(const float4* __restrict__ in, int grp) {
    const int limg  = blockIdx.x / BLOCKS_PER_IMG;
    const int chunk = blockIdx.x % BLOCKS_PER_IMG;
    const int img   = grp * IMG_PER_GRP + limg;
    const float4* __restrict__ p =
        in + (size_t)img * IMG_VEC4 + (size_t)chunk * CHUNK_VEC4;

    float s = 0.f, sq = 0.f;
    #pragma unroll 8
    for (int i = threadIdx.x; i < CHUNK_VEC4; i += RED_THREADS) {
        float4 v = __ldcg(p + i);          // evict-normal in L2: apply re-reads it
        s  += (v.x + v.y) + (v.z + v.w);
        sq += (v.x * v.x + v.y * v.y) + (v.z * v.z + v.w * v.w);
    }

    #pragma unroll
    for (int off = 16; off > 0; off >>= 1) {
        s  += __shfl_down_sync(0xffffffffu, s,  off);
        sq += __shfl_down_sync(0xffffffffu, sq, off);
    }
    __shared__ float2 warp_red[RED_THREADS / 32];
    const int lane = threadIdx.x & 31, wid = threadIdx.x >> 5;
    if (lane == 0) warp_red[wid] = make_float2(s, sq);
    __syncthreads();
    if (wid == 0) {
        float2 v = (lane < RED_THREADS / 32) ? warp_red[lane] : make_float2(0.f, 0.f);
        s = v.x; sq = v.y;
        #pragma unroll
        for (int off = 4; off > 0; off >>= 1) {
            s  += __shfl_down_sync(0xffffffffu, s,  off);
            sq += __shfl_down_sync(0xffffffffu, sq, off);
        }
        if (lane == 0) g_partials[img * BLOCKS_PER_IMG + chunk] = make_float2(s, sq);
    }
}

// -------- Apply one group --------
// Trigger at entry releases the NEXT reduce launch (full overlap: it has no
// dependency on us). Grid-dependency sync before loads guarantees reduce(g)'s
// partials are visible AND its lines are already in L2.
__global__ __launch_bounds__(APPLY_THREADS)
void apply_kernel(const float4* __restrict__ in, float4* __restrict__ out, int grp) {
    cudaTriggerProgrammaticLaunchCompletion();
    cudaGridDependencySynchronize();

    const int limg = blockIdx.x / APPLY_BLOCKS_PER_IMG;
    const int img  = grp * IMG_PER_GRP + limg;
    const size_t base = (size_t)img * IMG_VEC4 +
                        (size_t)(blockIdx.x % APPLY_BLOCKS_PER_IMG) * V4_PER_BLOCK +
                        threadIdx.x;

    // Front-batch loads: mostly L2 hits; .cs marks lines dead after read.
    float4 v[V4_PER_THREAD];
    #pragma unroll
    for (int k = 0; k < V4_PER_THREAD; ++k)
        v[k] = __ldcs(in + base + k * APPLY_THREADS);

    // Inline finalize: warp 0 reduces this image's 24 partials (fixed-order
    // tree -> deterministic, identical across all blocks of the image).
    __shared__ float2 sh_ss;
    if (threadIdx.x < 32) {
        const int lane = threadIdx.x;
        float s = 0.f, sq = 0.f;
        if (lane < BLOCKS_PER_IMG) {
            float2 p = g_partials[img * BLOCKS_PER_IMG + lane];
            s = p.x; sq = p.y;
        }
        #pragma unroll
        for (int off = 16; off > 0; off >>= 1) {
            s  += __shfl_down_sync(0xffffffffu, s,  off);
            sq += __shfl_down_sync(0xffffffffu, sq, off);
        }
        if (lane == 0) {
            const float inv_n = 1.0f / (float)IMG_ELEMS;
            float mean = s * inv_n;
            float var  = sq * inv_n - mean * mean;
            float stddev = sqrtf(fmaxf(var, 0.0f));
            const float min_std = 1.0f / sqrtf((float)IMG_ELEMS);
            float scale = 1.0f / fmaxf(stddev, min_std);
            sh_ss = make_float2(scale, -mean * scale);
        }
    }
    __syncthreads();
    const float scale = sh_ss.x, shift = sh_ss.y;

    #pragma unroll
    for (int k = 0; k < V4_PER_THREAD; ++k) {
        float4 r;
        r.x = fmaf(v[k].x, scale, shift);
        r.y = fmaf(v[k].y, scale, shift);
        r.z = fmaf(v[k].z, scale, shift);
        r.w = fmaf(v[k].w, scale, shift);
        __stcs(out + base + k * APPLY_THREADS, r);   // evict-first: spare the residue
    }
}

extern "C" void kernel_launch(void* const* d_in, const int* in_sizes, int n_in,
                              void* d_out, int out_size) {
    const float4* in = (const float4*)d_in[0];
    float4* out = (float4*)d_out;

    cudaLaunchAttribute attr[1];
    attr[0].id = cudaLaunchAttributeProgrammaticStreamSerialization;
    attr[0].val.programmaticStreamSerializationAllowed = 1;

    cudaLaunchConfig_t rcfg = {};
    rcfg.gridDim  = dim3(RED_BLOCKS, 1, 1);
    rcfg.blockDim = dim3(RED_THREADS, 1, 1);
    rcfg.attrs = attr; rcfg.numAttrs = 1;

    cudaLaunchConfig_t acfg = {};
    acfg.gridDim  = dim3(APPLY_BLOCKS, 1, 1);
    acfg.blockDim = dim3(APPLY_THREADS, 1, 1);
    acfg.attrs = attr; acfg.numAttrs = 1;

    for (int g = 0; g < GROUPS; ++g) {
        cudaLaunchKernelEx(&rcfg, partial_reduce_kernel, in, g);
        cudaLaunchKernelEx(&acfg, apply_kernel, in, out, g);
    }
}